// round 4
// baseline (speedup 1.0000x reference)
#include <cuda_runtime.h>

#define NMIX 160
#define MFIX 8192

// ---- gemm1: 64m x 160n tile, K-split 2, 64-k chunks (8 mma k-steps) ----
#define T1   256
#define BM1  64
#define KC   64
#define KSPL 2
#define AF1_SZ (8 * 4 * 128)    // 4096 floats
#define BF1_SZ (8 * 20 * 64)    // 10240 floats

// ---- gemm2: 64m x 256n tile per f ----
#define T2   256
#define BM2  64
#define BN2  256
#define HF_SZ (5 * 4 * 4 * 128) // 10240 floats
#define BF2_SZ (4 * 32 * 64)    // 8192 floats

// split-K partials of xk @ W1 (pre-tanh): [KSPL][M][NMIX]
__device__ float g_part[KSPL * MFIX * NMIX];

__device__ __forceinline__ float tf32r(float x) {
    unsigned u;
    asm("cvt.rna.tf32.f32 %0, %1;" : "=r"(u) : "f"(x));
    return __uint_as_float(u);
}

__device__ __forceinline__ void mma_tf32(float* c, const float4& a, const float2& b) {
    const unsigned* A = reinterpret_cast<const unsigned*>(&a);
    const unsigned* B = reinterpret_cast<const unsigned*>(&b);
    asm volatile(
        "mma.sync.aligned.m16n8k8.row.col.f32.tf32.tf32.f32 "
        "{%0,%1,%2,%3},{%4,%5,%6,%7},{%8,%9},{%0,%1,%2,%3};"
        : "+f"(c[0]), "+f"(c[1]), "+f"(c[2]), "+f"(c[3])
        : "r"(A[0]), "r"(A[1]), "r"(A[2]), "r"(A[3]), "r"(B[0]), "r"(B[1]));
}

// ---------------------------------------------------------------------------
// GEMM1 (split-K): partial[s][m,n] = sum_{k in split} xk[m,k] * W1[k,n]
// fragment-permuted smem; warp = 16m x 80n (10 n-tiles)
// ---------------------------------------------------------------------------
__global__ void __launch_bounds__(T1) k_gemm1(
    const float* __restrict__ x, const float* __restrict__ state,
    const float* __restrict__ tmx, const float* __restrict__ W1,
    const int* __restrict__ i_ptr, int S, int D, int rows, int Mtot)
{
    extern __shared__ float sm[];
    float* Af = sm;              // [8 ksteps][4 mg][128]
    float* Bf = sm + AF1_SZ;     // [8 ksteps][20 j][64]

    const int m0g   = blockIdx.x * BM1;
    const int kbase = blockIdx.y * (D / KSPL);
    const int tid   = threadIdx.x;
    const int w     = tid >> 5;
    const int lane  = tid & 31;
    const int wm    = w & 3;          // m-group (16 rows)
    const int wn    = w >> 2;         // n-half (80 cols)
    const int gq    = lane >> 2;      // groupID
    const int tig   = lane & 3;
    const int i1    = rows * i_ptr[0] + 1;

    float acc[10][4];
#pragma unroll
    for (int j = 0; j < 10; j++)
#pragma unroll
        for (int q = 0; q < 4; q++) acc[j][q] = 0.f;

    const int nc = (D / KSPL) / KC;

    for (int c = 0; c < nc; c++) {
        const int kb = kbase + c * KC;

        // ---- stage A (xk) in fragment-permuted layout: 64m x 64k ----
#pragma unroll
        for (int it = 0; it < 4; it++) {
            int idx = tid + it * T1;          // 1024 float4
            int m   = idx >> 4;
            int kq  = (idx & 15) * 4;
            int mg  = m0g + m;
            int g   = kb + kq;
            const float4 xv = *(const float4*)&x[(size_t)mg * D + g];
            float4 pv;
            if ((mg % S) == 0) {
                int b = mg / S;
                pv = *(const float4*)&state[((size_t)b * rows + i1) * D + g];
            } else {
                pv = *(const float4*)&x[(size_t)(mg - 1) * D + g];
            }
            const float4 tv = *(const float4*)&tmx[g];
            float v[4];
            v[0] = xv.x + (pv.x - xv.x) * tv.x;
            v[1] = xv.y + (pv.y - xv.y) * tv.y;
            v[2] = xv.z + (pv.z - xv.z) * tv.z;
            v[3] = xv.w + (pv.w - xv.w) * tv.w;
            int kstep = kq >> 3;
            int kh    = (kq >> 2) & 1;
            int ml    = m & 15, mgq = m >> 4;
            int gg    = ml & 7, row8 = ml >> 3;
            int base  = (kstep * 4 + mgq) * 128;
            int reg   = kh * 2 + row8;
#pragma unroll
            for (int e = 0; e < 4; e++)
                Af[base + (gg * 4 + e) * 4 + reg] = tf32r(v[e]);
        }

        // ---- stage B (W1) in fragment-permuted layout: 64k x 160n ----
#pragma unroll
        for (int it = 0; it < 10; it++) {
            int idx = tid + it * T1;          // 2560 float4
            int k   = idx / 40;
            int n4  = (idx - k * 40) * 4;
            const float4 wv = *(const float4*)&W1[(size_t)(kb + k) * NMIX + n4];
            int kstep = k >> 3;
            int kk    = k & 7;
            int tg    = kk & 3, rg = kk >> 2;
            float v[4] = { wv.x, wv.y, wv.z, wv.w };
#pragma unroll
            for (int e = 0; e < 4; e++) {
                int n = n4 + e;
                int j = n >> 3, g = n & 7;
                Bf[(kstep * 20 + j) * 64 + (g * 4 + tg) * 2 + rg] = tf32r(v[e]);
            }
        }
        __syncthreads();

        // ---- mma ----
#pragma unroll
        for (int ks = 0; ks < 8; ks++) {
            const float4 a = *(const float4*)&Af[(ks * 4 + wm) * 128 + lane * 4];
#pragma unroll
            for (int j = 0; j < 10; j++) {
                const float2 b = *(const float2*)&Bf[(ks * 20 + wn * 10 + j) * 64 + lane * 2];
                mma_tf32(acc[j], a, b);
            }
        }
        __syncthreads();
    }

    // ---- store partials ----
    float* gp = g_part + (size_t)blockIdx.y * Mtot * NMIX;
    const int r0 = m0g + wm * 16 + gq;
#pragma unroll
    for (int j = 0; j < 10; j++) {
        const int n = wn * 80 + j * 8 + tig * 2;
        *(float2*)&gp[(size_t)r0 * NMIX + n]       = make_float2(acc[j][0], acc[j][1]);
        *(float2*)&gp[(size_t)(r0 + 8) * NMIX + n] = make_float2(acc[j][2], acc[j][3]);
    }
}

// ---------------------------------------------------------------------------
// GEMM2 fused: h = tanh(part0+part1);  out[m,f,d] = x + sx*(maa_f + h_f @ W2_f)
// 64m x 256n tile; per-f B staging; warp = 16m x 128n (16 n-tiles)
// ---------------------------------------------------------------------------
__global__ void __launch_bounds__(T2) k_gemm2(
    const float* __restrict__ x, const float* __restrict__ state,
    const float* __restrict__ W2,
    const float* __restrict__ mk, const float* __restrict__ mw,
    const float* __restrict__ mv, const float* __restrict__ mr,
    const float* __restrict__ mg,
    const int* __restrict__ i_ptr, float* __restrict__ out,
    int S, int D, int rows, int Mtot)
{
    extern __shared__ float sm[];
    float* Hf = sm;              // [5 f][4 ksteps][4 mg][128]
    float* Bf = sm + HF_SZ;      // [4 ksteps][32 j][64]

    const int m0   = blockIdx.x * BM2;
    const int d0   = blockIdx.y * BN2;
    const int tid  = threadIdx.x;
    const int w    = tid >> 5;
    const int lane = tid & 31;
    const int wm   = w & 3;
    const int wn   = w >> 2;
    const int gq   = lane >> 2;
    const int tig  = lane & 3;
    const int i1   = rows * i_ptr[0] + 1;

    // ---- stage h = tanh(p0+p1) in fragment-permuted layout, all 5 f ----
#pragma unroll
    for (int it = 0; it < 10; it++) {
        int idx = tid + it * T2;             // 2560 float4
        int r   = idx / 40;
        int c4  = (idx - r * 40) * 4;
        const float4 a = *(const float4*)&g_part[(size_t)(m0 + r) * NMIX + c4];
        const float4 b = *(const float4*)&g_part[(size_t)(Mtot + m0 + r) * NMIX + c4];
        float v[4];
        v[0] = tanhf(a.x + b.x);
        v[1] = tanhf(a.y + b.y);
        v[2] = tanhf(a.z + b.z);
        v[3] = tanhf(a.w + b.w);
        int f     = c4 >> 5;
        int kloc  = c4 & 31;
        int kstep = kloc >> 3;
        int kh    = (kloc >> 2) & 1;
        int ml    = r & 15, mgq = r >> 4;
        int gg    = ml & 7, row8 = ml >> 3;
        int base  = f * 2048 + (kstep * 4 + mgq) * 128;
        int reg   = kh * 2 + row8;
#pragma unroll
        for (int e = 0; e < 4; e++)
            Hf[base + (gg * 4 + e) * 4 + reg] = tf32r(v[e]);
    }

    const float* maa[5] = { mk, mw, mv, mr, mg };

    for (int f = 0; f < 5; f++) {
        __syncthreads();   // Hf ready (f==0) / previous Bf consumed (f>0)

        // ---- stage W2_f slice [32k x 256n] fragment-permuted ----
#pragma unroll
        for (int it = 0; it < 8; it++) {
            int idx = tid + it * T2;         // 2048 float4
            int k   = idx >> 6;
            int n4  = (idx & 63) * 4;
            const float4 wv = *(const float4*)&W2[(size_t)(f * 32 + k) * D + d0 + n4];
            int kstep = k >> 3;
            int kk    = k & 7;
            int tg    = kk & 3, rg = kk >> 2;
            float v[4] = { wv.x, wv.y, wv.z, wv.w };
#pragma unroll
            for (int e = 0; e < 4; e++) {
                int n = n4 + e;
                int j = n >> 3, g = n & 7;
                Bf[(kstep * 32 + j) * 64 + (g * 4 + tg) * 2 + rg] = tf32r(v[e]);
            }
        }
        __syncthreads();

        float acc[16][4];
#pragma unroll
        for (int j = 0; j < 16; j++)
#pragma unroll
            for (int q = 0; q < 4; q++) acc[j][q] = 0.f;

#pragma unroll
        for (int ks = 0; ks < 4; ks++) {
            const float4 a = *(const float4*)&Hf[f * 2048 + (ks * 4 + wm) * 128 + lane * 4];
#pragma unroll
            for (int j = 0; j < 16; j++) {
                const float2 b = *(const float2*)&Bf[(ks * 32 + wn * 16 + j) * 64 + lane * 2];
                mma_tf32(acc[j], a, b);
            }
        }

        // ---- epilogue: out = x + sx*(maa + y) ----
        const float* mf = maa[f];
#pragma unroll 4
        for (int j = 0; j < 16; j++) {
            const int d = d0 + (wn * 16 + j) * 8 + tig * 2;
            const float2 m2 = *(const float2*)&mf[d];
#pragma unroll
            for (int half = 0; half < 2; half++) {
                const int mr_ = m0 + wm * 16 + gq + half * 8;
                const float2 xv = *(const float2*)&x[(size_t)mr_ * D + d];
                float2 pv;
                if ((mr_ % S) == 0) {
                    int b = mr_ / S;
                    pv = *(const float2*)&state[((size_t)b * rows + i1) * D + d];
                } else {
                    pv = *(const float2*)&x[(size_t)(mr_ - 1) * D + d];
                }
                const float y0 = acc[j][half * 2];
                const float y1 = acc[j][half * 2 + 1];
                float2 o;
                o.x = xv.x + (pv.x - xv.x) * (m2.x + y0);
                o.y = xv.y + (pv.y - xv.y) * (m2.y + y1);
                *(float2*)&out[((size_t)mr_ * 5 + f) * D + d] = o;
            }
        }
    }
}

// ---------------------------------------------------------------------------
// state copy with row i1 <- x[:, S-1, :]
// ---------------------------------------------------------------------------
__global__ void k_state(const float* __restrict__ x,
                        const float* __restrict__ state,
                        const int* __restrict__ i_ptr,
                        float* __restrict__ out_state,
                        int S, int D, int rows, int total4)
{
    int idx = blockIdx.x * blockDim.x + threadIdx.x;
    if (idx >= total4) return;
    int e  = idx * 4;
    int dd = e % D;
    int r  = (e / D) % rows;
    int b  = e / (D * rows);
    int i1 = rows * i_ptr[0] + 1;
    float4 v;
    if (r == i1)
        v = *(const float4*)&x[((size_t)b * S + (S - 1)) * D + dd];
    else
        v = *(const float4*)&state[e];
    *(float4*)&out_state[e] = v;
}

// ---------------------------------------------------------------------------
extern "C" void kernel_launch(void* const* d_in, const int* in_sizes, int n_in,
                              void* d_out, int out_size)
{
    const float* x     = (const float*)d_in[0];
    const float* state = (const float*)d_in[1];
    const float* tmx   = (const float*)d_in[2];
    const float* W1    = (const float*)d_in[3];
    const float* W2    = (const float*)d_in[4];
    const float* mk    = (const float*)d_in[5];
    const float* mw    = (const float*)d_in[6];
    const float* mv    = (const float*)d_in[7];
    const float* mr    = (const float*)d_in[8];
    const float* mg    = (const float*)d_in[9];
    const int*   ip    = (const int*)d_in[10];

    const int D    = in_sizes[2];          // 2048
    const int M    = in_sizes[0] / D;      // 8192
    const int rows = 2 + D / 32;           // 66
    const int B    = in_sizes[1] / (rows * D);
    const int S    = M / B;

    float* out_x = (float*)d_out;
    const long long xsz = (long long)M * 5 * D;

    const int smem1 = (AF1_SZ + BF1_SZ) * 4;   // 57344 B
    const int smem2 = (HF_SZ + BF2_SZ) * 4;    // 73728 B
    static int inited = 0;
    if (!inited) {
        cudaFuncSetAttribute(k_gemm1, cudaFuncAttributeMaxDynamicSharedMemorySize, smem1);
        cudaFuncSetAttribute(k_gemm2, cudaFuncAttributeMaxDynamicSharedMemorySize, smem2);
        inited = 1;
    }

    dim3 g1(M / BM1, KSPL);
    k_gemm1<<<g1, T1, smem1>>>(x, state, tmx, W1, ip, S, D, rows, M);

    dim3 g2(M / BM2, D / BN2);
    k_gemm2<<<g2, T2, smem2>>>(x, state, W2, mk, mw, mv, mr, mg, ip, out_x, S, D, rows, M);

    if ((long long)out_size > xsz) {
        float* out_state = out_x + xsz;
        int total4 = (B * rows * D) / 4;
        k_state<<<(total4 + 255) / 256, 256>>>(x, state, ip, out_state, S, D, rows, total4);
    }
}

// round 5
// speedup vs baseline: 1.5111x; 1.5111x over previous
#include <cuda_runtime.h>

#define NMIX 160
// gemm1: 64m x 160n x K=2048, KC=32 chunks
#define T1   256
#define BM1  64
#define KC1  32
#define A_PAD 36     // 36 mod 32 = 4 -> conflict-free fragment loads
#define B_PAD 164
// gemm2: 64m x 256n per f
#define T2   256
#define BM2  64
#define BN2  256
#define H_PAD 164
#define W_PAD 260
#define HS_FLOATS (BM2 * H_PAD)            // 10496
#define WS_FLOATS (32 * W_PAD)             // 8320

// h = tanh(xk @ W1): [M][NMIX], M = 8192
__device__ float g_h[8192 * NMIX];

__device__ __forceinline__ float tf32r(float x) {
    unsigned u;
    asm("cvt.rna.tf32.f32 %0, %1;" : "=r"(u) : "f"(x));
    return __uint_as_float(u);
}

__device__ __forceinline__ void mma_tf32(float* c, const float4& a, const float2& b) {
    const unsigned* A = reinterpret_cast<const unsigned*>(&a);
    const unsigned* B = reinterpret_cast<const unsigned*>(&b);
    asm volatile(
        "mma.sync.aligned.m16n8k8.row.col.f32.tf32.tf32.f32 "
        "{%0,%1,%2,%3},{%4,%5,%6,%7},{%8,%9},{%0,%1,%2,%3};"
        : "+f"(c[0]), "+f"(c[1]), "+f"(c[2]), "+f"(c[3])
        : "r"(A[0]), "r"(A[1]), "r"(A[2]), "r"(A[3]), "r"(B[0]), "r"(B[1]));
}

// ---------------------------------------------------------------------------
// GEMM1: g_h[m,n] = tanh( sum_k xk[m,k] * W1[k,n] )
// 8 warps = 4 m-groups x 2 n-halves (80n each); row-major smem, pad mod32=4
// ---------------------------------------------------------------------------
__global__ void __launch_bounds__(T1) k_gemm1(
    const float* __restrict__ x, const float* __restrict__ state,
    const float* __restrict__ tmx, const float* __restrict__ W1,
    const int* __restrict__ i_ptr, int S, int D, int rows)
{
    __shared__ alignas(16) float xk_s[BM1][A_PAD];
    __shared__ alignas(16) float w1_s[KC1][B_PAD];

    const int m0g  = blockIdx.x * BM1;
    const int tid  = threadIdx.x;
    const int w    = tid >> 5;
    const int lane = tid & 31;
    const int wm   = w & 3;
    const int wn   = w >> 2;
    const int gq   = lane >> 2;
    const int tig  = lane & 3;
    const int i1   = rows * i_ptr[0] + 1;

    // staging thread mapping
    const int sa_kq = (tid & 7) * 4;     // A: k quad
    const int sa_m  = tid >> 3;          // A: row (0..31) ; two iters -> +32
    const int sb_k  = tid / 40;          // B base mapping via idx

    float acc[10][4];
#pragma unroll
    for (int j = 0; j < 10; j++)
#pragma unroll
        for (int q = 0; q < 4; q++) acc[j][q] = 0.f;

    float4 xv[2], pv[2], tv[2];
    float4 wv[5];
    int    wk[5], wn4[5];

    const int nc = D / KC1;

#define LDG1(KB)                                                              \
    {                                                                         \
        _Pragma("unroll")                                                     \
        for (int it = 0; it < 2; it++) {                                      \
            int m  = sa_m + it * 32;                                          \
            int mg = m0g + m;                                                 \
            int g  = (KB) + sa_kq;                                            \
            xv[it] = *(const float4*)&x[(size_t)mg * D + g];                  \
            if ((mg % S) == 0) {                                              \
                int b = mg / S;                                               \
                pv[it] = *(const float4*)&state[((size_t)b * rows + i1) * D + g]; \
            } else {                                                          \
                pv[it] = *(const float4*)&x[(size_t)(mg - 1) * D + g];        \
            }                                                                 \
            tv[it] = *(const float4*)&tmx[g];                                 \
        }                                                                     \
        _Pragma("unroll")                                                     \
        for (int it = 0; it < 5; it++) {                                      \
            int idx = tid + it * T1;                                          \
            int k   = idx / 40;                                               \
            int n4  = (idx - k * 40) * 4;                                     \
            wk[it] = k; wn4[it] = n4;                                         \
            wv[it] = *(const float4*)&W1[(size_t)((KB) + k) * NMIX + n4];     \
        }                                                                     \
    }

#define STS1()                                                                \
    {                                                                         \
        _Pragma("unroll")                                                     \
        for (int it = 0; it < 2; it++) {                                      \
            int m = sa_m + it * 32;                                           \
            float4 v;                                                         \
            v.x = tf32r(xv[it].x + (pv[it].x - xv[it].x) * tv[it].x);         \
            v.y = tf32r(xv[it].y + (pv[it].y - xv[it].y) * tv[it].y);         \
            v.z = tf32r(xv[it].z + (pv[it].z - xv[it].z) * tv[it].z);         \
            v.w = tf32r(xv[it].w + (pv[it].w - xv[it].w) * tv[it].w);         \
            *(float4*)&xk_s[m][sa_kq] = v;                                    \
        }                                                                     \
        _Pragma("unroll")                                                     \
        for (int it = 0; it < 5; it++) {                                      \
            float4 v;                                                         \
            v.x = tf32r(wv[it].x); v.y = tf32r(wv[it].y);                     \
            v.z = tf32r(wv[it].z); v.w = tf32r(wv[it].w);                     \
            *(float4*)&w1_s[wk[it]][wn4[it]] = v;                             \
        }                                                                     \
    }

    LDG1(0);

    for (int c = 0; c < nc; c++) {
        __syncthreads();
        STS1();
        __syncthreads();
        if (c + 1 < nc) LDG1((c + 1) * KC1);

        const int r0 = wm * 16 + gq;
#pragma unroll
        for (int ks = 0; ks < 4; ks++) {
            const int k0 = ks * 8;
            float4 af;
            af.x = xk_s[r0][k0 + tig];
            af.y = xk_s[r0 + 8][k0 + tig];
            af.z = xk_s[r0][k0 + tig + 4];
            af.w = xk_s[r0 + 8][k0 + tig + 4];
#pragma unroll
            for (int j = 0; j < 10; j++) {
                const int n = wn * 80 + j * 8 + gq;
                float2 b;
                b.x = w1_s[k0 + tig][n];
                b.y = w1_s[k0 + tig + 4][n];
                mma_tf32(acc[j], af, b);
            }
        }
    }

    // epilogue: tanh -> g_h
    const int r0g = m0g + wm * 16 + gq;
#pragma unroll
    for (int j = 0; j < 10; j++) {
        const int n = wn * 80 + j * 8 + tig * 2;
        *(float2*)&g_h[(size_t)r0g * NMIX + n] =
            make_float2(tanhf(acc[j][0]), tanhf(acc[j][1]));
        *(float2*)&g_h[(size_t)(r0g + 8) * NMIX + n] =
            make_float2(tanhf(acc[j][2]), tanhf(acc[j][3]));
    }
#undef LDG1
#undef STS1
}

// ---------------------------------------------------------------------------
// GEMM2 fused: out[m,f,d] = x + sx*(maa_f + h_f @ W2_f)
// 64m x 256n tile; 8 warps = 4m x 2n(128 each); per-f W2 staging w/ prefetch
// ---------------------------------------------------------------------------
__global__ void __launch_bounds__(T2) k_gemm2(
    const float* __restrict__ x, const float* __restrict__ state,
    const float* __restrict__ W2,
    const float* __restrict__ mk, const float* __restrict__ mw,
    const float* __restrict__ mv, const float* __restrict__ mr,
    const float* __restrict__ mg,
    const int* __restrict__ i_ptr, float* __restrict__ out,
    int S, int D, int rows)
{
    extern __shared__ float sm[];
    float (*h_s)[H_PAD]  = (float (*)[H_PAD])sm;
    float (*w2_s)[W_PAD] = (float (*)[W_PAD])(sm + HS_FLOATS);

    const int m0   = blockIdx.x * BM2;
    const int d0   = blockIdx.y * BN2;
    const int tid  = threadIdx.x;
    const int w    = tid >> 5;
    const int lane = tid & 31;
    const int wm   = w & 3;
    const int wn   = w >> 2;
    const int gq   = lane >> 2;
    const int tig  = lane & 3;
    const int i1   = rows * i_ptr[0] + 1;

    // W2 staging mapping: 2048 float4 / 256 thr = 8
    const int sw_k  = tid >> 5;          // wrong granularity; use idx form below
    (void)sw_k;

    float4 wv[8];

#define LDG2(F)                                                               \
    {                                                                         \
        _Pragma("unroll")                                                     \
        for (int it = 0; it < 8; it++) {                                      \
            int idx = tid + it * T2;                                          \
            int k   = idx >> 6;                                               \
            int n4  = (idx & 63) * 4;                                         \
            wv[it] = *(const float4*)&W2[(size_t)((F) * 32 + k) * D + d0 + n4]; \
        }                                                                     \
    }

#define STS2()                                                                \
    {                                                                         \
        _Pragma("unroll")                                                     \
        for (int it = 0; it < 8; it++) {                                      \
            int idx = tid + it * T2;                                          \
            int k   = idx >> 6;                                               \
            int n4  = (idx & 63) * 4;                                         \
            float4 v;                                                         \
            v.x = tf32r(wv[it].x); v.y = tf32r(wv[it].y);                     \
            v.z = tf32r(wv[it].z); v.w = tf32r(wv[it].w);                     \
            *(float4*)&w2_s[k][n4] = v;                                       \
        }                                                                     \
    }

    LDG2(0);

    // stage h tile (already tanh'ed): 64 x 160
#pragma unroll
    for (int it = 0; it < 10; it++) {
        int idx = tid + it * T2;             // 2560 float4
        int r   = idx / 40;
        int c4  = (idx - r * 40) * 4;
        const float4 hv = *(const float4*)&g_h[(size_t)(m0 + r) * NMIX + c4];
        float4 v;
        v.x = tf32r(hv.x); v.y = tf32r(hv.y);
        v.z = tf32r(hv.z); v.w = tf32r(hv.w);
        *(float4*)&h_s[r][c4] = v;
    }

    const float* maa[5] = { mk, mw, mv, mr, mg };

    for (int f = 0; f < 5; f++) {
        __syncthreads();     // h_s ready (f=0) / previous mma done (f>0)
        STS2();
        __syncthreads();
        if (f < 4) LDG2(f + 1);

        float acc[16][4];
#pragma unroll
        for (int j = 0; j < 16; j++)
#pragma unroll
            for (int q = 0; q < 4; q++) acc[j][q] = 0.f;

        const int r0 = wm * 16 + gq;
#pragma unroll
        for (int ks = 0; ks < 4; ks++) {
            const int kc = f * 32 + ks * 8;
            float4 af;
            af.x = h_s[r0][kc + tig];
            af.y = h_s[r0 + 8][kc + tig];
            af.z = h_s[r0][kc + tig + 4];
            af.w = h_s[r0 + 8][kc + tig + 4];
#pragma unroll
            for (int j = 0; j < 16; j++) {
                const int n = wn * 128 + j * 8 + gq;
                float2 b;
                b.x = w2_s[ks * 8 + tig][n];
                b.y = w2_s[ks * 8 + tig + 4][n];
                mma_tf32(acc[j], af, b);
            }
        }

        // epilogue: out = x + sx*(maa + y)
        const float* mf = maa[f];
#pragma unroll 4
        for (int j = 0; j < 16; j++) {
            const int d = d0 + wn * 128 + j * 8 + tig * 2;
            const float2 m2 = *(const float2*)&mf[d];
#pragma unroll
            for (int half = 0; half < 2; half++) {
                const int mr_ = m0 + wm * 16 + gq + half * 8;
                const float2 xvv = *(const float2*)&x[(size_t)mr_ * D + d];
                float2 pvv;
                if ((mr_ % S) == 0) {
                    int b = mr_ / S;
                    pvv = *(const float2*)&state[((size_t)b * rows + i1) * D + d];
                } else {
                    pvv = *(const float2*)&x[(size_t)(mr_ - 1) * D + d];
                }
                const float y0 = acc[j][half * 2];
                const float y1 = acc[j][half * 2 + 1];
                float2 o;
                o.x = xvv.x + (pvv.x - xvv.x) * (m2.x + y0);
                o.y = xvv.y + (pvv.y - xvv.y) * (m2.y + y1);
                *(float2*)&out[((size_t)mr_ * 5 + f) * D + d] = o;
            }
        }
    }
#undef LDG2
#undef STS2
}

// ---------------------------------------------------------------------------
// state copy with row i1 <- x[:, S-1, :]
// ---------------------------------------------------------------------------
__global__ void k_state(const float* __restrict__ x,
                        const float* __restrict__ state,
                        const int* __restrict__ i_ptr,
                        float* __restrict__ out_state,
                        int S, int D, int rows, int total4)
{
    int idx = blockIdx.x * blockDim.x + threadIdx.x;
    if (idx >= total4) return;
    int e  = idx * 4;
    int dd = e % D;
    int r  = (e / D) % rows;
    int b  = e / (D * rows);
    int i1 = rows * i_ptr[0] + 1;
    float4 v;
    if (r == i1)
        v = *(const float4*)&x[((size_t)b * S + (S - 1)) * D + dd];
    else
        v = *(const float4*)&state[e];
    *(float4*)&out_state[e] = v;
}

// ---------------------------------------------------------------------------
extern "C" void kernel_launch(void* const* d_in, const int* in_sizes, int n_in,
                              void* d_out, int out_size)
{
    const float* x     = (const float*)d_in[0];
    const float* state = (const float*)d_in[1];
    const float* tmx   = (const float*)d_in[2];
    const float* W1    = (const float*)d_in[3];
    const float* W2    = (const float*)d_in[4];
    const float* mk    = (const float*)d_in[5];
    const float* mw    = (const float*)d_in[6];
    const float* mv    = (const float*)d_in[7];
    const float* mr    = (const float*)d_in[8];
    const float* mg    = (const float*)d_in[9];
    const int*   ip    = (const int*)d_in[10];

    const int D    = in_sizes[2];          // 2048
    const int M    = in_sizes[0] / D;      // 8192
    const int rows = 2 + D / 32;           // 66
    const int B    = in_sizes[1] / (rows * D);
    const int S    = M / B;

    float* out_x = (float*)d_out;
    const long long xsz = (long long)M * 5 * D;

    const int smem2 = (HS_FLOATS + WS_FLOATS) * 4;   // 75264 B
    static int inited = 0;
    if (!inited) {
        cudaFuncSetAttribute(k_gemm2, cudaFuncAttributeMaxDynamicSharedMemorySize, smem2);
        inited = 1;
    }

    k_gemm1<<<M / BM1, T1>>>(x, state, tmx, W1, ip, S, D, rows);

    dim3 g2(M / BM2, D / BN2);
    k_gemm2<<<g2, T2, smem2>>>(x, state, W2, mk, mw, mv, mr, mg, ip, out_x, S, D, rows);

    if ((long long)out_size > xsz) {
        float* out_state = out_x + xsz;
        int total4 = (B * rows * D) / 4;
        k_state<<<(total4 + 255) / 256, 256>>>(x, state, ip, out_state, S, D, rows, total4);
    }
}

// round 6
// speedup vs baseline: 2.6384x; 1.7460x over previous
#include <cuda_runtime.h>

#define NMIX 160
// gemm1: 64m x 160n, KC=64, 512 threads = 4m x 4n warps, j=5
#define T1    512
#define BM1   64
#define KC1   64
#define A1PAD 68     // mod 32 = 4  (A-frag conflict-free)
#define B1PAD 168    // mod 32 = 8  (B-frag conflict-free)
#define SM1_FLOATS (BM1 * A1PAD + KC1 * B1PAD)
// gemm2: 64m x 64n, 256 threads = 4m x 2n warps, j=4, all 5 f resident
#define T2    256
#define BM2   64
#define BN2   64
#define HPAD  164    // mod 32 = 4
#define WPAD  72     // mod 32 = 8
#define SM2_FLOATS (BM2 * HPAD + 160 * WPAD)

// h = tanh(xk @ W1): [M][NMIX], M = 8192
__device__ float g_h[8192 * NMIX];

__device__ __forceinline__ float tf32r(float x) {
    unsigned u;
    asm("cvt.rna.tf32.f32 %0, %1;" : "=r"(u) : "f"(x));
    return __uint_as_float(u);
}

__device__ __forceinline__ void mma_tf32(float* c, const float4& a, const float2& b) {
    const unsigned* A = reinterpret_cast<const unsigned*>(&a);
    const unsigned* B = reinterpret_cast<const unsigned*>(&b);
    asm volatile(
        "mma.sync.aligned.m16n8k8.row.col.f32.tf32.tf32.f32 "
        "{%0,%1,%2,%3},{%4,%5,%6,%7},{%8,%9},{%0,%1,%2,%3};"
        : "+f"(c[0]), "+f"(c[1]), "+f"(c[2]), "+f"(c[3])
        : "r"(A[0]), "r"(A[1]), "r"(A[2]), "r"(A[3]), "r"(B[0]), "r"(B[1]));
}

// ---------------------------------------------------------------------------
// GEMM1: g_h[m,n] = tanh( sum_k xk[m,k] * W1[k,n] )
// ---------------------------------------------------------------------------
__global__ void __launch_bounds__(T1, 1) k_gemm1(
    const float* __restrict__ x, const float* __restrict__ state,
    const float* __restrict__ tmx, const float* __restrict__ W1,
    const int* __restrict__ i_ptr, int S, int D, int rows)
{
    extern __shared__ float sm[];
    float (*xk_s)[A1PAD] = (float (*)[A1PAD])sm;
    float (*w1_s)[B1PAD] = (float (*)[B1PAD])(sm + BM1 * A1PAD);

    const int m0g  = blockIdx.x * BM1;
    const int tid  = threadIdx.x;
    const int w    = tid >> 5;
    const int lane = tid & 31;
    const int wm   = w & 3;          // 4 m-groups of 16
    const int wn   = w >> 2;         // 4 n-groups of 40
    const int gq   = lane >> 2;
    const int tig  = lane & 3;
    const int i1   = rows * i_ptr[0] + 1;

    // A staging: 1024 float4, 2/thread;  B staging: 2560 float4, 5/thread
    const int sa_m  = tid >> 4;          // +32 on 2nd iter
    const int sa_kq = (tid & 15) * 4;

    float acc[5][4];
#pragma unroll
    for (int j = 0; j < 5; j++)
#pragma unroll
        for (int q = 0; q < 4; q++) acc[j][q] = 0.f;

    float4 xv[2], pv[2], tv[2];
    float4 wv[5];
    int    wk[5], wn4[5];

    const int nc = D / KC1;

#define LDG1(KB)                                                              \
    {                                                                         \
        _Pragma("unroll")                                                     \
        for (int it = 0; it < 2; it++) {                                      \
            int m  = sa_m + it * 32;                                          \
            int mg = m0g + m;                                                 \
            int g  = (KB) + sa_kq;                                            \
            xv[it] = *(const float4*)&x[(size_t)mg * D + g];                  \
            if ((mg % S) == 0) {                                              \
                int b = mg / S;                                               \
                pv[it] = *(const float4*)&state[((size_t)b * rows + i1) * D + g]; \
            } else {                                                          \
                pv[it] = *(const float4*)&x[(size_t)(mg - 1) * D + g];        \
            }                                                                 \
            tv[it] = *(const float4*)&tmx[g];                                 \
        }                                                                     \
        _Pragma("unroll")                                                     \
        for (int it = 0; it < 5; it++) {                                      \
            int idx = tid + it * T1;                                          \
            int k   = idx / 40;                                               \
            int n4  = (idx - k * 40) * 4;                                     \
            wk[it] = k; wn4[it] = n4;                                         \
            wv[it] = *(const float4*)&W1[(size_t)((KB) + k) * NMIX + n4];     \
        }                                                                     \
    }

#define STS1()                                                                \
    {                                                                         \
        _Pragma("unroll")                                                     \
        for (int it = 0; it < 2; it++) {                                      \
            int m = sa_m + it * 32;                                           \
            float4 v;                                                         \
            v.x = tf32r(xv[it].x + (pv[it].x - xv[it].x) * tv[it].x);         \
            v.y = tf32r(xv[it].y + (pv[it].y - xv[it].y) * tv[it].y);         \
            v.z = tf32r(xv[it].z + (pv[it].z - xv[it].z) * tv[it].z);         \
            v.w = tf32r(xv[it].w + (pv[it].w - xv[it].w) * tv[it].w);         \
            *(float4*)&xk_s[m][sa_kq] = v;                                    \
        }                                                                     \
        _Pragma("unroll")                                                     \
        for (int it = 0; it < 5; it++) {                                      \
            float4 v;                                                         \
            v.x = tf32r(wv[it].x); v.y = tf32r(wv[it].y);                     \
            v.z = tf32r(wv[it].z); v.w = tf32r(wv[it].w);                     \
            *(float4*)&w1_s[wk[it]][wn4[it]] = v;                             \
        }                                                                     \
    }

    LDG1(0);

    for (int c = 0; c < nc; c++) {
        __syncthreads();
        STS1();
        __syncthreads();
        if (c + 1 < nc) LDG1((c + 1) * KC1);

        const int r0 = wm * 16 + gq;
#pragma unroll
        for (int ks = 0; ks < 8; ks++) {
            const int k0 = ks * 8;
            float4 af;
            af.x = xk_s[r0][k0 + tig];
            af.y = xk_s[r0 + 8][k0 + tig];
            af.z = xk_s[r0][k0 + tig + 4];
            af.w = xk_s[r0 + 8][k0 + tig + 4];
#pragma unroll
            for (int j = 0; j < 5; j++) {
                const int n = wn * 40 + j * 8 + gq;
                float2 b;
                b.x = w1_s[k0 + tig][n];
                b.y = w1_s[k0 + tig + 4][n];
                mma_tf32(acc[j], af, b);
            }
        }
    }

    const int r0g = m0g + wm * 16 + gq;
#pragma unroll
    for (int j = 0; j < 5; j++) {
        const int n = wn * 40 + j * 8 + tig * 2;
        *(float2*)&g_h[(size_t)r0g * NMIX + n] =
            make_float2(tanhf(acc[j][0]), tanhf(acc[j][1]));
        *(float2*)&g_h[(size_t)(r0g + 8) * NMIX + n] =
            make_float2(tanhf(acc[j][2]), tanhf(acc[j][3]));
    }
#undef LDG1
#undef STS1
}

// ---------------------------------------------------------------------------
// GEMM2 fused: out[m,f,d] = x + sx*(maa_f + h_f @ W2_f)
// 64m x 64n block; all 5 f accumulated together; f-innermost epilogue
// ---------------------------------------------------------------------------
__global__ void __launch_bounds__(T2, 2) k_gemm2(
    const float* __restrict__ x, const float* __restrict__ state,
    const float* __restrict__ W2,
    const float* __restrict__ mk, const float* __restrict__ mw,
    const float* __restrict__ mv, const float* __restrict__ mr,
    const float* __restrict__ mg,
    const int* __restrict__ i_ptr, float* __restrict__ out,
    int S, int D, int rows)
{
    extern __shared__ float sm[];
    float (*h_s)[HPAD]  = (float (*)[HPAD])sm;
    float (*w2_s)[WPAD] = (float (*)[WPAD])(sm + BM2 * HPAD);

    const int m0   = blockIdx.x * BM2;
    const int d0   = blockIdx.y * BN2;
    const int tid  = threadIdx.x;
    const int w    = tid >> 5;
    const int lane = tid & 31;
    const int wm   = w & 3;          // 4 m-groups of 16
    const int wn   = w >> 2;         // 2 n-groups of 32
    const int gq   = lane >> 2;
    const int tig  = lane & 3;
    const int i1   = rows * i_ptr[0] + 1;

    // stage h tile: 64 x 160 = 2560 float4, 10/thread
#pragma unroll
    for (int it = 0; it < 10; it++) {
        int idx = tid + it * T2;
        int r   = idx / 40;
        int c4  = (idx - r * 40) * 4;
        const float4 hv = *(const float4*)&g_h[(size_t)(m0 + r) * NMIX + c4];
        float4 v;
        v.x = tf32r(hv.x); v.y = tf32r(hv.y);
        v.z = tf32r(hv.z); v.w = tf32r(hv.w);
        *(float4*)&h_s[r][c4] = v;
    }
    // stage W2 (all 5 f): 160 x 64 = 2560 float4, 10/thread
#pragma unroll
    for (int it = 0; it < 10; it++) {
        int idx = tid + it * T2;
        int k   = idx >> 4;              // 0..159
        int n4  = (idx & 15) * 4;
        const float4 wvv = *(const float4*)&W2[(size_t)k * D + d0 + n4];
        float4 v;
        v.x = tf32r(wvv.x); v.y = tf32r(wvv.y);
        v.z = tf32r(wvv.z); v.w = tf32r(wvv.w);
        *(float4*)&w2_s[k][n4] = v;
    }
    __syncthreads();

    float acc[5][4][4];
#pragma unroll
    for (int f = 0; f < 5; f++)
#pragma unroll
        for (int j = 0; j < 4; j++)
#pragma unroll
            for (int q = 0; q < 4; q++) acc[f][j][q] = 0.f;

    const int r0 = wm * 16 + gq;
#pragma unroll
    for (int f = 0; f < 5; f++) {
#pragma unroll
        for (int ks = 0; ks < 4; ks++) {
            const int kc = f * 32 + ks * 8;
            float4 af;
            af.x = h_s[r0][kc + tig];
            af.y = h_s[r0 + 8][kc + tig];
            af.z = h_s[r0][kc + tig + 4];
            af.w = h_s[r0 + 8][kc + tig + 4];
#pragma unroll
            for (int j = 0; j < 4; j++) {
                const int n = wn * 32 + j * 8 + gq;
                float2 b;
                b.x = w2_s[kc + tig][n];
                b.y = w2_s[kc + tig + 4][n];
                mma_tf32(acc[f][j], af, b);
            }
        }
    }

    // epilogue: f innermost, x/prev loaded once per (j,half)
    const float* maa[5] = { mk, mw, mv, mr, mg };
#pragma unroll
    for (int j = 0; j < 4; j++) {
        const int d = d0 + wn * 32 + j * 8 + tig * 2;
        float2 m2[5];
#pragma unroll
        for (int f = 0; f < 5; f++) m2[f] = *(const float2*)&maa[f][d];
#pragma unroll
        for (int half = 0; half < 2; half++) {
            const int mr_ = m0 + wm * 16 + gq + half * 8;
            const float2 xvv = *(const float2*)&x[(size_t)mr_ * D + d];
            float2 pvv;
            if ((mr_ % S) == 0) {
                int b = mr_ / S;
                pvv = *(const float2*)&state[((size_t)b * rows + i1) * D + d];
            } else {
                pvv = *(const float2*)&x[(size_t)(mr_ - 1) * D + d];
            }
            const float sx0 = pvv.x - xvv.x;
            const float sx1 = pvv.y - xvv.y;
#pragma unroll
            for (int f = 0; f < 5; f++) {
                float2 o;
                o.x = xvv.x + sx0 * (m2[f].x + acc[f][j][half * 2]);
                o.y = xvv.y + sx1 * (m2[f].y + acc[f][j][half * 2 + 1]);
                *(float2*)&out[((size_t)mr_ * 5 + f) * D + d] = o;
            }
        }
    }
}

// ---------------------------------------------------------------------------
// state copy with row i1 <- x[:, S-1, :]
// ---------------------------------------------------------------------------
__global__ void k_state(const float* __restrict__ x,
                        const float* __restrict__ state,
                        const int* __restrict__ i_ptr,
                        float* __restrict__ out_state,
                        int S, int D, int rows, int total4)
{
    int idx = blockIdx.x * blockDim.x + threadIdx.x;
    if (idx >= total4) return;
    int e  = idx * 4;
    int dd = e % D;
    int r  = (e / D) % rows;
    int b  = e / (D * rows);
    int i1 = rows * i_ptr[0] + 1;
    float4 v;
    if (r == i1)
        v = *(const float4*)&x[((size_t)b * S + (S - 1)) * D + dd];
    else
        v = *(const float4*)&state[e];
    *(float4*)&out_state[e] = v;
}

// ---------------------------------------------------------------------------
extern "C" void kernel_launch(void* const* d_in, const int* in_sizes, int n_in,
                              void* d_out, int out_size)
{
    const float* x     = (const float*)d_in[0];
    const float* state = (const float*)d_in[1];
    const float* tmx   = (const float*)d_in[2];
    const float* W1    = (const float*)d_in[3];
    const float* W2    = (const float*)d_in[4];
    const float* mk    = (const float*)d_in[5];
    const float* mw    = (const float*)d_in[6];
    const float* mv    = (const float*)d_in[7];
    const float* mr    = (const float*)d_in[8];
    const float* mg    = (const float*)d_in[9];
    const int*   ip    = (const int*)d_in[10];

    const int D    = in_sizes[2];          // 2048
    const int M    = in_sizes[0] / D;      // 8192
    const int rows = 2 + D / 32;           // 66
    const int B    = in_sizes[1] / (rows * D);
    const int S    = M / B;

    float* out_x = (float*)d_out;
    const long long xsz = (long long)M * 5 * D;

    const int smem1 = SM1_FLOATS * 4;      // (64*68 + 64*168)*4 = 60416 B
    const int smem2 = SM2_FLOATS * 4;      // (64*164 + 160*72)*4 = 88064 B
    static int inited = 0;
    if (!inited) {
        cudaFuncSetAttribute(k_gemm1, cudaFuncAttributeMaxDynamicSharedMemorySize, smem1);
        cudaFuncSetAttribute(k_gemm2, cudaFuncAttributeMaxDynamicSharedMemorySize, smem2);
        inited = 1;
    }

    k_gemm1<<<M / BM1, T1, smem1>>>(x, state, tmx, W1, ip, S, D, rows);

    dim3 g2(M / BM2, D / BN2);
    k_gemm2<<<g2, T2, smem2>>>(x, state, W2, mk, mw, mv, mr, mg, ip, out_x, S, D, rows);

    if ((long long)out_size > xsz) {
        float* out_state = out_x + xsz;
        int total4 = (B * rows * D) / 4;
        k_state<<<(total4 + 255) / 256, 256>>>(x, state, ip, out_state, S, D, rows, total4);
    }
}